// round 8
// baseline (speedup 1.0000x reference)
#include <cuda_runtime.h>

#define N 8192
#define THREADS 256
#define F4_PER_ROW (N / 4)            // 2048 float4 per row
#define ITERS (F4_PER_ROW / THREADS)  // 8 float4 per thread
#define LOG2E 1.44269504088896340736f
#define LN2   0.69314718055994530942f

__device__ float g_accum;             // zero at load; reset by last block each run
__device__ int   g_counter;           // zero at load; reset by last block each run

// softplus in log2 units: log2(1 + 2^x) = max(x,0) + log2(1 + 2^(-|x|))
// (R6 encoding: EX2 + LG2; 1 MUFU slot beats 3 FFMA slots — measured R7)
__device__ __forceinline__ float softplus2(float x) {
    float e = exp2f(0.0f - fabsf(x));
    return fmaxf(x, 0.0f) + __log2f(1.0f + e);
}

__global__ void __launch_bounds__(THREADS, 8)
bt_row_kernel(const float* __restrict__ win,
              const float* __restrict__ betas,
              float* __restrict__ out) {
    const int row = blockIdx.x;
    const float bi   = __ldg(betas + row);
    const float nbiL = -bi * LOG2E;           // block-uniform

    const float4* wrow = reinterpret_cast<const float4*>(win) + (size_t)row * F4_PER_ROW;
    const float4* b4   = reinterpret_cast<const float4*>(betas);

    float acc0 = 0.0f, acc1 = 0.0f;

    #pragma unroll
    for (int k = 0; k < ITERS; k++) {
        const int p = k * THREADS + threadIdx.x;
        float4 w  = __ldcs(wrow + p);         // streaming, zero reuse
        float4 bj = __ldg(b4 + p);            // L1/L2-resident

        float x0 = fmaf(bj.x, LOG2E, nbiL);
        float x1 = fmaf(bj.y, LOG2E, nbiL);
        float x2 = fmaf(bj.z, LOG2E, nbiL);
        float x3 = fmaf(bj.w, LOG2E, nbiL);

        acc0 = fmaf(w.x, softplus2(x0), acc0);
        acc1 = fmaf(w.y, softplus2(x1), acc1);
        acc0 = fmaf(w.z, softplus2(x2), acc0);
        acc1 = fmaf(w.w, softplus2(x3), acc1);
    }

    float acc = acc0 + acc1;

    // Remove the diagonal term (j == row), recomputed with identical FP ops so
    // the cancellation is exact.
    if (threadIdx.x == 0) {
        float wd = __ldg(win + (size_t)row * N + row);
        float xd = fmaf(bi, LOG2E, nbiL);
        acc -= wd * softplus2(xd);
    }

    // warp reduction
    #pragma unroll
    for (int off = 16; off > 0; off >>= 1)
        acc += __shfl_xor_sync(0xFFFFFFFFu, acc, off);

    __shared__ float warp_sums[THREADS / 32];
    const int lane = threadIdx.x & 31;
    const int wid  = threadIdx.x >> 5;
    if (lane == 0) warp_sums[wid] = acc;
    __syncthreads();

    // Single-node fused finalization. No __threadfence (MEMBAR drains the
    // in-flight LDG stream — measured 6.8us in R5). Instead:
    //   RED(relaxed) partial  ->  atom(acq_rel) counter
    // The release on the counter atomic orders the RED; the last block's
    // acquire makes all partials visible.
    if (threadIdx.x == 0) {
        float v = warp_sums[0];
        #pragma unroll
        for (int i = 1; i < THREADS / 32; i++) v += warp_sums[i];

        asm volatile("red.relaxed.gpu.add.f32 [%0], %1;"
                     :: "l"(&g_accum), "f"(v) : "memory");
        int prev;
        asm volatile("atom.acq_rel.gpu.add.s32 %0, [%1], %2;"
                     : "=r"(prev) : "l"(&g_counter), "r"(1) : "memory");

        if (prev == N - 1) {                  // last block: all partials visible
            float total = *((volatile float*)&g_accum);
            *out = total * LN2;               // overwrite poison with plain store
            g_accum   = 0.0f;                 // reset for next graph replay
            g_counter = 0;                    // (kernel-end membar orders these)
        }
    }
}

extern "C" void kernel_launch(void* const* d_in, const int* in_sizes, int n_in,
                              void* d_out, int out_size) {
    const float* win   = (const float*)d_in[0];
    const float* betas = (const float*)d_in[1];
    float* out = (float*)d_out;

    bt_row_kernel<<<N, THREADS>>>(win, betas, out);   // single graph node
}

// round 10
// speedup vs baseline: 1.0067x; 1.0067x over previous
#include <cuda_runtime.h>

#define N 8192
#define THREADS 256
#define F4_PER_ROW (N / 4)            // 2048 float4 per row
#define ITERS (F4_PER_ROW / THREADS)  // 8 float4 per thread
#define LOG2E 1.44269504088896340736f
#define LN2   0.69314718055994530942f

__device__ float g_accum;             // zero at load; reset by last block each run
__device__ int   g_counter;           // zero at load; reset by last block each run

// softplus in log2 units: log2(1 + 2^x) = max(x,0) + log2(1 + 2^(-|x|))
__device__ __forceinline__ float softplus2(float x) {
    float e = exp2f(0.0f - fabsf(x));
    return fmaxf(x, 0.0f) + __log2f(1.0f + e);
}

__global__ void __launch_bounds__(THREADS, 8)
bt_row_kernel(const float* __restrict__ win,
              const float* __restrict__ betas,
              float* __restrict__ out) {
    const int row = blockIdx.x;
    const float bi   = __ldg(betas + row);
    const float nbiL = -bi * LOG2E;           // block-uniform

    const float4* wrow = reinterpret_cast<const float4*>(win) + (size_t)row * F4_PER_ROW;
    const float4* b4   = reinterpret_cast<const float4*>(betas);

    float acc0 = 0.0f, acc1 = 0.0f;

    #pragma unroll
    for (int k = 0; k < ITERS; k++) {
        const int p = k * THREADS + threadIdx.x;
        float4 w  = __ldcs(wrow + p);         // streaming, zero reuse
        float4 bj = __ldg(b4 + p);            // L1/L2-resident

        float x0 = fmaf(bj.x, LOG2E, nbiL);
        float x1 = fmaf(bj.y, LOG2E, nbiL);
        float x2 = fmaf(bj.z, LOG2E, nbiL);
        float x3 = fmaf(bj.w, LOG2E, nbiL);

        acc0 = fmaf(w.x, softplus2(x0), acc0);
        acc1 = fmaf(w.y, softplus2(x1), acc1);
        acc0 = fmaf(w.z, softplus2(x2), acc0);
        acc1 = fmaf(w.w, softplus2(x3), acc1);
    }

    float acc = acc0 + acc1;

    // Remove the diagonal term (j == row), recomputed with identical FP ops so
    // the cancellation is exact.
    if (threadIdx.x == 0) {
        float wd = __ldg(win + (size_t)row * N + row);
        float xd = fmaf(bi, LOG2E, nbiL);
        acc -= wd * softplus2(xd);
    }

    // warp reduction
    #pragma unroll
    for (int off = 16; off > 0; off >>= 1)
        acc += __shfl_xor_sync(0xFFFFFFFFu, acc, off);

    __shared__ float warp_sums[THREADS / 32];
    const int lane = threadIdx.x & 31;
    const int wid  = threadIdx.x >> 5;
    if (lane == 0) warp_sums[wid] = acc;
    __syncthreads();

    // Asymmetric-cost finalization:
    //  - 8192x: relaxed RED + RELEASE counter add (release orders only this
    //    thread's prior writes = the RED; no L1 invalidation -> betas stay hot)
    //  - 1x: acquire fence in the last block only, then read/write/reset.
    if (threadIdx.x == 0) {
        float v = warp_sums[0];
        #pragma unroll
        for (int i = 1; i < THREADS / 32; i++) v += warp_sums[i];

        asm volatile("red.relaxed.gpu.add.f32 [%0], %1;"
                     :: "l"(&g_accum), "f"(v) : "memory");
        int prev;
        asm volatile("atom.release.gpu.add.s32 %0, [%1], %2;"
                     : "=r"(prev) : "l"(&g_counter), "r"(1) : "memory");

        if (prev == N - 1) {                  // last block
            asm volatile("fence.acq_rel.gpu;" ::: "memory");  // single acquire
            float total = *((volatile float*)&g_accum);
            *out = total * LN2;               // overwrite poison with plain store
            g_accum   = 0.0f;                 // reset for next graph replay
            g_counter = 0;                    // kernel-end ordering covers these
        }
    }
}

extern "C" void kernel_launch(void* const* d_in, const int* in_sizes, int n_in,
                              void* d_out, int out_size) {
    const float* win   = (const float*)d_in[0];
    const float* betas = (const float*)d_in[1];
    float* out = (float*)d_out;

    bt_row_kernel<<<N, THREADS>>>(win, betas, out);   // single graph node
}

// round 11
// speedup vs baseline: 1.0506x; 1.0435x over previous
#include <cuda_runtime.h>

#define N 8192
#define THREADS 256
#define F4_PER_ROW (N / 4)            // 2048 float4 per row
#define ITERS (F4_PER_ROW / THREADS)  // 8 float4 per thread
#define LOG2E 1.44269504088896340736f
#define LN2   0.69314718055994530942f

// Packed accumulator: bits[50:64) = block count, bits[0:50) = sum * 2^19.
// One relaxed 64-bit atomicAdd per block does BOTH the reduction and the
// last-block election; the atomic return value hands the last block the
// complete total with no fence/acquire/release anywhere (L2 per-address
// serialization is the only synchronization needed). Integer adds commute
// exactly -> bitwise-deterministic result.
#define SUM_SCALE  524288.0f          // 2^19
#define COUNT_UNIT (1ULL << 50)
#define SUM_MASK   (COUNT_UNIT - 1ULL)

__device__ unsigned long long g_pack; // zero at load; reset by last block each run

// softplus in log2 units: log2(1 + 2^x) = max(x,0) + log2(1 + 2^(-|x|))
__device__ __forceinline__ float softplus2(float x) {
    float e = exp2f(0.0f - fabsf(x));
    return fmaxf(x, 0.0f) + __log2f(1.0f + e);
}

__global__ void __launch_bounds__(THREADS, 8)
bt_row_kernel(const float* __restrict__ win,
              const float* __restrict__ betas,
              float* __restrict__ out) {
    const int row = blockIdx.x;
    const float bi   = __ldg(betas + row);
    const float nbiL = -bi * LOG2E;           // block-uniform

    const float4* wrow = reinterpret_cast<const float4*>(win) + (size_t)row * F4_PER_ROW;
    const float4* b4   = reinterpret_cast<const float4*>(betas);

    float acc0 = 0.0f, acc1 = 0.0f;

    #pragma unroll
    for (int k = 0; k < ITERS; k++) {
        const int p = k * THREADS + threadIdx.x;
        float4 w  = __ldcs(wrow + p);         // streaming, zero reuse
        float4 bj = __ldg(b4 + p);            // L1/L2-resident

        float x0 = fmaf(bj.x, LOG2E, nbiL);
        float x1 = fmaf(bj.y, LOG2E, nbiL);
        float x2 = fmaf(bj.z, LOG2E, nbiL);
        float x3 = fmaf(bj.w, LOG2E, nbiL);

        acc0 = fmaf(w.x, softplus2(x0), acc0);
        acc1 = fmaf(w.y, softplus2(x1), acc1);
        acc0 = fmaf(w.z, softplus2(x2), acc0);
        acc1 = fmaf(w.w, softplus2(x3), acc1);
    }

    float acc = acc0 + acc1;

    // Remove the diagonal term (j == row), recomputed with identical FP ops so
    // the cancellation is exact.
    if (threadIdx.x == 0) {
        float wd = __ldg(win + (size_t)row * N + row);
        float xd = fmaf(bi, LOG2E, nbiL);
        acc -= wd * softplus2(xd);
    }

    // warp reduction
    #pragma unroll
    for (int off = 16; off > 0; off >>= 1)
        acc += __shfl_xor_sync(0xFFFFFFFFu, acc, off);

    __shared__ float warp_sums[THREADS / 32];
    const int lane = threadIdx.x & 31;
    const int wid  = threadIdx.x >> 5;
    if (lane == 0) warp_sums[wid] = acc;
    __syncthreads();

    // Single relaxed 64-bit atomic: reduction + election + handoff in one op.
    if (threadIdx.x == 0) {
        float v = warp_sums[0];
        #pragma unroll
        for (int i = 1; i < THREADS / 32; i++) v += warp_sums[i];

        // v >= 0 (all products non-negative; diagonal subtraction removes a
        // term contained in the sum), so unsigned fixed-point is safe.
        unsigned long long myfix =
            (unsigned long long)(fmaxf(v, 0.0f) * SUM_SCALE + 0.5f);
        unsigned long long old = atomicAdd(&g_pack, COUNT_UNIT + myfix);

        if ((old >> 50) == (unsigned long long)(N - 1)) {   // last block
            unsigned long long total = (old & SUM_MASK) + myfix;
            *out = (float)((double)total * ((double)LN2 / 524288.0));
            g_pack = 0ULL;                    // reset for next graph replay;
        }                                     // kernel-boundary orders this store
    }
}

extern "C" void kernel_launch(void* const* d_in, const int* in_sizes, int n_in,
                              void* d_out, int out_size) {
    const float* win   = (const float*)d_in[0];
    const float* betas = (const float*)d_in[1];
    float* out = (float*)d_out;

    bt_row_kernel<<<N, THREADS>>>(win, betas, out);   // single graph node
}